// round 10
// baseline (speedup 1.0000x reference)
#include <cuda_runtime.h>

#define BB 16
#define SS 4096
#define HH 1024

// scratch: per-segment partial dec_fea [4][B][H]
__device__ float g_part[4 * BB * HH];
// work-stealing counters: [0] = scores, [1] = context
__device__ unsigned int g_ctr[2];

#define NTILES 4096      // 16 b * 128 s-chunks * 2 h-halves
#define PERSIST_GRID 1184  // 148 SMs * 8 blocks

__device__ __forceinline__ float tanh_fast(float x) {
    float y;
    asm("tanh.approx.f32 %0, %1;" : "=f"(y) : "f"(x));
    return y;
}

__device__ __forceinline__ float warp_sum(float v) {
#pragma unroll
    for (int o = 16; o > 0; o >>= 1) v += __shfl_xor_sync(0xffffffffu, v, o);
    return v;
}

__device__ __forceinline__ float warp_max(float v) {
#pragma unroll
    for (int o = 16; o > 0; o >>= 1) v = fmaxf(v, __shfl_xor_sync(0xffffffffu, v, o));
    return v;
}

// ---------------------------------------------------------------------------
// K1: split-K decode projection. grid (128, 4).
// Also zeroes scores region and resets the work-stealing counters.
// ---------------------------------------------------------------------------
__global__ void k_decproj(const float* __restrict__ s_t,
                          const float* __restrict__ W,
                          const float* __restrict__ bias,
                          float* __restrict__ scores) {
    if (blockIdx.x == 0 && blockIdx.y == 0 && threadIdx.x == 0) {
        g_ctr[0] = 0u;
        g_ctr[1] = 0u;
    }
    // zero scores: 512 blocks x 128 lanes = 65536
    if (threadIdx.x < 128) {
        int gid = (blockIdx.x * 4 + blockIdx.y) * 128 + threadIdx.x;
        scores[gid] = 0.f;
    }

    int warp = threadIdx.x >> 5, lane = threadIdx.x & 31;
    int h   = blockIdx.x * 8 + warp;
    int seg = blockIdx.y;
    int k0  = seg * 64;

    float acc[BB];
#pragma unroll
    for (int b = 0; b < BB; b++) acc[b] = 0.f;

    const float4* Wrow = reinterpret_cast<const float4*>(W + (size_t)h * HH);
#pragma unroll
    for (int it = 0; it < 2; it++) {
        int k4 = k0 + it * 32 + lane;
        float4 w = __ldg(Wrow + k4);
#pragma unroll
        for (int b = 0; b < BB; b++) {
            float4 s4 = __ldg(reinterpret_cast<const float4*>(s_t + b * HH) + k4);
            acc[b] += w.x * s4.x + w.y * s4.y + w.z * s4.z + w.w * s4.w;
        }
    }
    float bi = (seg == 0) ? __ldg(bias + h) : 0.f;
#pragma unroll
    for (int b = 0; b < BB; b++) {
        float r = warp_sum(acc[b]);
        if (lane == 0) g_part[(seg * BB + b) * HH + h] = r + bi;
    }
}

// ---------------------------------------------------------------------------
// K2: scores[b][s] += sum_{h in slice} tanh(ef + dec + cov*Wc) * v
// PERSISTENT work-stealing: 1184 blocks pull 32-row x h-half tiles from
// g_ctr[0] until the 4096 tiles are gone (tail ~ 1 tile, not 1 wave).
// Flat 8-row LDG batch (MLP 8) inside each tile; merged butterflies + REDG.
// ---------------------------------------------------------------------------
__device__ __forceinline__ void butterfly4_atomic(float a0, float a1, float a2,
                                                  float a3, int lane,
                                                  float* dst) {
    float x01 = (lane & 16) ? a1 : a0;
    float y01 = (lane & 16) ? a0 : a1;
    x01 += __shfl_xor_sync(0xffffffffu, y01, 16);
    float x23 = (lane & 16) ? a3 : a2;
    float y23 = (lane & 16) ? a2 : a3;
    x23 += __shfl_xor_sync(0xffffffffu, y23, 16);
    float m0 = (lane & 8) ? x23 : x01;
    float m1 = (lane & 8) ? x01 : x23;
    m0 += __shfl_xor_sync(0xffffffffu, m1, 8);
    m0 += __shfl_xor_sync(0xffffffffu, m0, 4);
    m0 += __shfl_xor_sync(0xffffffffu, m0, 2);
    m0 += __shfl_xor_sync(0xffffffffu, m0, 1);
    if ((lane & 7) == 0) {
        int r = ((lane >> 4) & 1) | ((lane >> 2) & 2);
        atomicAdd(dst + r, m0);
    }
}

__global__ void __launch_bounds__(128, 8) k_scores(const float* __restrict__ ef,
                                                   const float* __restrict__ cov,
                                                   const float* __restrict__ Wc,
                                                   const float* __restrict__ v,
                                                   float* __restrict__ scores) {
    int lane = threadIdx.x & 31;
    __shared__ unsigned int s_idx;

    for (;;) {
        if (threadIdx.x == 0) s_idx = atomicAdd(&g_ctr[0], 1u);
        __syncthreads();
        unsigned int idx = s_idx;
        __syncthreads();
        if (idx >= NTILES) return;

        int b    = idx >> 8;            // 16 batches
        int rem  = idx & 255;
        int sblk = rem >> 1;            // 128 s-chunks of 32
        int half = rem & 1;
        int s0   = sblk * 32;
        int t    = half * 128 + threadIdx.x;

        // per-tile operands (L1/L2-hot)
        float4 p0 = __ldg(reinterpret_cast<const float4*>(g_part + (0 * BB + b) * HH) + t);
        float4 p1 = __ldg(reinterpret_cast<const float4*>(g_part + (1 * BB + b) * HH) + t);
        float4 p2 = __ldg(reinterpret_cast<const float4*>(g_part + (2 * BB + b) * HH) + t);
        float4 p3 = __ldg(reinterpret_cast<const float4*>(g_part + (3 * BB + b) * HH) + t);
        float4 d4;
        d4.x = (p0.x + p1.x) + (p2.x + p3.x);
        d4.y = (p0.y + p1.y) + (p2.y + p3.y);
        d4.z = (p0.z + p1.z) + (p2.z + p3.z);
        d4.w = (p0.w + p1.w) + (p2.w + p3.w);
        float4 w4 = __ldg(reinterpret_cast<const float4*>(Wc) + t);
        float4 v4 = __ldg(reinterpret_cast<const float4*>(v) + t);

        const float4* efb  = reinterpret_cast<const float4*>(ef + ((size_t)b * SS) * HH);
        const float4* cov4 = reinterpret_cast<const float4*>(cov + b * SS + s0);
        float* sc = scores + b * SS + s0;

#pragma unroll 1
        for (int g = 0; g < 4; g++) {   // 4 groups of 8 rows = 32 rows
            float4 f[8];
#pragma unroll
            for (int r = 0; r < 8; r++)
                f[r] = __ldg(efb + (size_t)(s0 + g * 8 + r) * (HH / 4) + t);
            float4 c4a = __ldg(cov4 + g * 2);
            float4 c4b = __ldg(cov4 + g * 2 + 1);

            const float cr[8] = {c4a.x, c4a.y, c4a.z, c4a.w,
                                 c4b.x, c4b.y, c4b.z, c4b.w};
            float acc[8];
#pragma unroll
            for (int r = 0; r < 8; r++) {
                float c = cr[r];
                float e0 = tanh_fast(f[r].x + fmaf(c, w4.x, d4.x));
                float e1 = tanh_fast(f[r].y + fmaf(c, w4.y, d4.y));
                float e2 = tanh_fast(f[r].z + fmaf(c, w4.z, d4.z));
                float e3 = tanh_fast(f[r].w + fmaf(c, w4.w, d4.w));
                acc[r] = fmaf(e0, v4.x, fmaf(e1, v4.y, fmaf(e2, v4.z, e3 * v4.w)));
            }
            butterfly4_atomic(acc[0], acc[1], acc[2], acc[3], lane, sc + g * 8);
            butterfly4_atomic(acc[4], acc[5], acc[6], acc[7], lane, sc + g * 8 + 4);
        }
    }
}

// ---------------------------------------------------------------------------
// K3: masked softmax + renorm; writes attn twice; zeroes c_t.
// ---------------------------------------------------------------------------
__global__ void k_softmax(const float* __restrict__ mask, float* __restrict__ out) {
    int b   = blockIdx.x;
    int tid = threadIdx.x;
    const float4* sc = reinterpret_cast<const float4*>(out + BB * HH + 2 * BB * SS + b * SS);
    float4* attn1 = reinterpret_cast<float4*>(out + BB * HH + b * SS);
    float4* attn2 = reinterpret_cast<float4*>(out + BB * HH + BB * SS + b * SS);
    const float4* m4p = reinterpret_cast<const float4*>(mask + b * SS);

    __shared__ float red[32];
    int warp = tid >> 5, lane = tid & 31;

    float4 x = sc[tid];

    float mx = fmaxf(fmaxf(x.x, x.y), fmaxf(x.z, x.w));
    mx = warp_max(mx);
    if (lane == 0) red[warp] = mx;
    __syncthreads();
    if (tid < 32) {
        float t = red[tid];
        t = warp_max(t);
        if (tid == 0) red[0] = t;
    }
    __syncthreads();
    mx = red[0];
    __syncthreads();

    float4 p;
    p.x = __expf(x.x - mx); p.y = __expf(x.y - mx);
    p.z = __expf(x.z - mx); p.w = __expf(x.w - mx);

    float sm = p.x + p.y + p.z + p.w;
    sm = warp_sum(sm);
    if (lane == 0) red[warp] = sm;
    __syncthreads();
    if (tid < 32) {
        float t = red[tid];
        t = warp_sum(t);
        if (tid == 0) red[0] = t;
    }
    __syncthreads();
    float denom = red[0];
    __syncthreads();

    float4 m = m4p[tid];
    float4 a0;
    float inv = 1.f / denom;
    a0.x = p.x * inv * m.x; a0.y = p.y * inv * m.y;
    a0.z = p.z * inv * m.z; a0.w = p.w * inv * m.w;

    float s2 = a0.x + a0.y + a0.z + a0.w;
    s2 = warp_sum(s2);
    if (lane == 0) red[warp] = s2;
    __syncthreads();
    if (tid < 32) {
        float t = red[tid];
        t = warp_sum(t);
        if (tid == 0) red[0] = t;
    }
    __syncthreads();
    float inv2 = 1.f / (red[0] + 1e-20f);

    float4 a;
    a.x = a0.x * inv2; a.y = a0.y * inv2; a.z = a0.z * inv2; a.w = a0.w * inv2;
    attn1[tid] = a;
    attn2[tid] = a;

    out[b * HH + tid] = 0.f;
}

// ---------------------------------------------------------------------------
// K4: c_t[b][h] += sum_s attn[b,s] * eo[b,s,h]
// PERSISTENT work-stealing over the same 4096-tile decomposition.
// ---------------------------------------------------------------------------
__global__ void __launch_bounds__(128, 8) k_context(const float* __restrict__ eo,
                                                    float* __restrict__ out) {
    __shared__ unsigned int s_idx;

    for (;;) {
        if (threadIdx.x == 0) s_idx = atomicAdd(&g_ctr[1], 1u);
        __syncthreads();
        unsigned int idx = s_idx;
        __syncthreads();
        if (idx >= NTILES) return;

        int b    = idx >> 8;
        int rem  = idx & 255;
        int sblk = rem >> 1;
        int half = rem & 1;
        int s0   = sblk * 32;
        int t    = half * 128 + threadIdx.x;

        const float* attn = out + BB * HH + b * SS;
        const float4* eob = reinterpret_cast<const float4*>(eo + ((size_t)b * SS) * HH);

        float4 acc = make_float4(0.f, 0.f, 0.f, 0.f);
#pragma unroll 4
        for (int i = 0; i < 32; i++) {
            int s = s0 + i;
            float a  = __ldg(attn + s);
            float4 e = __ldg(eob + (size_t)s * (HH / 4) + t);
            acc.x += a * e.x; acc.y += a * e.y;
            acc.z += a * e.z; acc.w += a * e.w;
        }
        float* ct = out + b * HH + t * 4;
        atomicAdd(ct + 0, acc.x);
        atomicAdd(ct + 1, acc.y);
        atomicAdd(ct + 2, acc.z);
        atomicAdd(ct + 3, acc.w);
    }
}

// ---------------------------------------------------------------------------
extern "C" void kernel_launch(void* const* d_in, const int* in_sizes, int n_in,
                              void* d_out, int out_size) {
    const float* s_t_hat = (const float*)d_in[0];
    const float* enc_out = (const float*)d_in[1];
    const float* enc_fea = (const float*)d_in[2];
    const float* mask    = (const float*)d_in[3];
    const float* cov     = (const float*)d_in[4];
    const float* W_dec   = (const float*)d_in[5];
    const float* b_dec   = (const float*)d_in[6];
    const float* W_c     = (const float*)d_in[7];
    const float* v       = (const float*)d_in[8];
    float* out = (float*)d_out;

    float* scores = out + BB * HH + 2 * BB * SS;

    k_decproj<<<dim3(128, 4), 256>>>(s_t_hat, W_dec, b_dec, scores);
    k_scores<<<PERSIST_GRID, 128>>>(enc_fea, cov, W_c, v, scores);
    k_softmax<<<BB, 1024>>>(mask, out);
    k_context<<<PERSIST_GRID, 128>>>(enc_out, out);
}

// round 11
// speedup vs baseline: 1.1382x; 1.1382x over previous
#include <cuda_runtime.h>

#define BB 16
#define SS 4096
#define HH 1024

// scratch: per-segment partial dec_fea [4][B][H]
__device__ float g_part[4 * BB * HH];

__device__ __forceinline__ float tanh_fast(float x) {
    float y;
    asm("tanh.approx.f32 %0, %1;" : "=f"(y) : "f"(x));
    return y;
}

// streaming (evict-first) float4 load for zero-reuse tensors
__device__ __forceinline__ float4 ldcs4(const float4* p) {
    float4 r;
    asm("ld.global.cs.v4.f32 {%0,%1,%2,%3}, [%4];"
        : "=f"(r.x), "=f"(r.y), "=f"(r.z), "=f"(r.w) : "l"(p));
    return r;
}

__device__ __forceinline__ float warp_sum(float v) {
#pragma unroll
    for (int o = 16; o > 0; o >>= 1) v += __shfl_xor_sync(0xffffffffu, v, o);
    return v;
}

__device__ __forceinline__ float warp_max(float v) {
#pragma unroll
    for (int o = 16; o > 0; o >>= 1) v = fmaxf(v, __shfl_xor_sync(0xffffffffu, v, o));
    return v;
}

// ---------------------------------------------------------------------------
// K1: split-K decode projection. grid (128, 4).
// Each warp computes partial dec[b][h] over a 256-wide k segment for all 16
// batches -> g_part[seg][b][h]; bias folded into segment 0.
// Also zeroes the scores region for K2's atomics.
// ---------------------------------------------------------------------------
__global__ void k_decproj(const float* __restrict__ s_t,
                          const float* __restrict__ W,
                          const float* __restrict__ bias,
                          float* __restrict__ scores) {
    // zero scores: 512 blocks x 128 lanes = 65536
    if (threadIdx.x < 128) {
        int gid = (blockIdx.x * 4 + blockIdx.y) * 128 + threadIdx.x;
        scores[gid] = 0.f;
    }

    int warp = threadIdx.x >> 5, lane = threadIdx.x & 31;
    int h   = blockIdx.x * 8 + warp;
    int seg = blockIdx.y;
    int k0  = seg * 64;   // float4 index of segment start

    float acc[BB];
#pragma unroll
    for (int b = 0; b < BB; b++) acc[b] = 0.f;

    const float4* Wrow = reinterpret_cast<const float4*>(W + (size_t)h * HH);
#pragma unroll
    for (int it = 0; it < 2; it++) {
        int k4 = k0 + it * 32 + lane;
        float4 w = __ldg(Wrow + k4);
#pragma unroll
        for (int b = 0; b < BB; b++) {
            float4 s4 = __ldg(reinterpret_cast<const float4*>(s_t + b * HH) + k4);
            acc[b] += w.x * s4.x + w.y * s4.y + w.z * s4.z + w.w * s4.w;
        }
    }
    float bi = (seg == 0) ? __ldg(bias + h) : 0.f;
#pragma unroll
    for (int b = 0; b < BB; b++) {
        float r = warp_sum(acc[b]);
        if (lane == 0) g_part[(seg * BB + b) * HH + h] = r + bi;
    }
}

// ---------------------------------------------------------------------------
// K2: scores[b][s] += sum_{h in slice} tanh(ef + dec + cov*Wc) * v
// Static grid (R9 best): flat 8-row LDG batch (MLP 8), scalar compute,
// merged 4-row butterflies + REDG atomics; ef streamed with ld.global.cs.
// launch_bounds(128,8): 8 blocks/SM resident.
// ---------------------------------------------------------------------------
#define SC_CHUNK 64

__device__ __forceinline__ void butterfly4_atomic(float a0, float a1, float a2,
                                                  float a3, int lane,
                                                  float* dst) {
    // merged 4-row butterfly: 5 shfl total
    float x01 = (lane & 16) ? a1 : a0;
    float y01 = (lane & 16) ? a0 : a1;
    x01 += __shfl_xor_sync(0xffffffffu, y01, 16);
    float x23 = (lane & 16) ? a3 : a2;
    float y23 = (lane & 16) ? a2 : a3;
    x23 += __shfl_xor_sync(0xffffffffu, y23, 16);
    float m0 = (lane & 8) ? x23 : x01;
    float m1 = (lane & 8) ? x01 : x23;
    m0 += __shfl_xor_sync(0xffffffffu, m1, 8);
    m0 += __shfl_xor_sync(0xffffffffu, m0, 4);
    m0 += __shfl_xor_sync(0xffffffffu, m0, 2);
    m0 += __shfl_xor_sync(0xffffffffu, m0, 1);
    // lane 0 -> row0, lane 16 -> row1, lane 8 -> row2, lane 24 -> row3
    if ((lane & 7) == 0) {
        int r = ((lane >> 4) & 1) | ((lane >> 2) & 2);
        atomicAdd(dst + r, m0);
    }
}

__global__ void __launch_bounds__(128, 8) k_scores(const float* __restrict__ ef,
                                                   const float* __restrict__ cov,
                                                   const float* __restrict__ Wc,
                                                   const float* __restrict__ v,
                                                   float* __restrict__ scores) {
    int b  = blockIdx.y;
    int s0 = blockIdx.x * SC_CHUNK;
    int t  = blockIdx.z * 128 + threadIdx.x;   // float4 index within h row
    int lane = threadIdx.x & 31;

    // gather dec from 4 split-K partials
    float4 p0 = __ldg(reinterpret_cast<const float4*>(g_part + (0 * BB + b) * HH) + t);
    float4 p1 = __ldg(reinterpret_cast<const float4*>(g_part + (1 * BB + b) * HH) + t);
    float4 p2 = __ldg(reinterpret_cast<const float4*>(g_part + (2 * BB + b) * HH) + t);
    float4 p3 = __ldg(reinterpret_cast<const float4*>(g_part + (3 * BB + b) * HH) + t);
    float4 d4;
    d4.x = (p0.x + p1.x) + (p2.x + p3.x);
    d4.y = (p0.y + p1.y) + (p2.y + p3.y);
    d4.z = (p0.z + p1.z) + (p2.z + p3.z);
    d4.w = (p0.w + p1.w) + (p2.w + p3.w);
    float4 w4 = __ldg(reinterpret_cast<const float4*>(Wc) + t);
    float4 v4 = __ldg(reinterpret_cast<const float4*>(v) + t);

    const float4* efb  = reinterpret_cast<const float4*>(ef + ((size_t)b * SS) * HH);
    const float4* cov4 = reinterpret_cast<const float4*>(cov + b * SS + s0);
    float* sc = scores + b * SS + s0;

#pragma unroll 1
    for (int g = 0; g < SC_CHUNK / 8; g++) {
        // ---- load phase: 8 independent streaming LDG.128 + 2 cov loads ----
        float4 f[8];
#pragma unroll
        for (int r = 0; r < 8; r++)
            f[r] = ldcs4(efb + (size_t)(s0 + g * 8 + r) * (HH / 4) + t);
        float4 c4a = __ldg(cov4 + g * 2);
        float4 c4b = __ldg(cov4 + g * 2 + 1);

        // ---- compute phase ----
        const float cr[8] = {c4a.x, c4a.y, c4a.z, c4a.w,
                             c4b.x, c4b.y, c4b.z, c4b.w};
        float acc[8];
#pragma unroll
        for (int r = 0; r < 8; r++) {
            float c = cr[r];
            float e0 = tanh_fast(f[r].x + fmaf(c, w4.x, d4.x));
            float e1 = tanh_fast(f[r].y + fmaf(c, w4.y, d4.y));
            float e2 = tanh_fast(f[r].z + fmaf(c, w4.z, d4.z));
            float e3 = tanh_fast(f[r].w + fmaf(c, w4.w, d4.w));
            acc[r] = fmaf(e0, v4.x, fmaf(e1, v4.y, fmaf(e2, v4.z, e3 * v4.w)));
        }
        butterfly4_atomic(acc[0], acc[1], acc[2], acc[3], lane, sc + g * 8);
        butterfly4_atomic(acc[4], acc[5], acc[6], acc[7], lane, sc + g * 8 + 4);
    }
}

// ---------------------------------------------------------------------------
// K3: masked softmax + renorm; writes attn twice; zeroes c_t.
// ---------------------------------------------------------------------------
__global__ void k_softmax(const float* __restrict__ mask, float* __restrict__ out) {
    int b   = blockIdx.x;
    int tid = threadIdx.x;
    const float4* sc = reinterpret_cast<const float4*>(out + BB * HH + 2 * BB * SS + b * SS);
    float4* attn1 = reinterpret_cast<float4*>(out + BB * HH + b * SS);
    float4* attn2 = reinterpret_cast<float4*>(out + BB * HH + BB * SS + b * SS);
    const float4* m4p = reinterpret_cast<const float4*>(mask + b * SS);

    __shared__ float red[32];
    int warp = tid >> 5, lane = tid & 31;

    float4 x = sc[tid];

    float mx = fmaxf(fmaxf(x.x, x.y), fmaxf(x.z, x.w));
    mx = warp_max(mx);
    if (lane == 0) red[warp] = mx;
    __syncthreads();
    if (tid < 32) {
        float t = red[tid];
        t = warp_max(t);
        if (tid == 0) red[0] = t;
    }
    __syncthreads();
    mx = red[0];
    __syncthreads();

    float4 p;
    p.x = __expf(x.x - mx); p.y = __expf(x.y - mx);
    p.z = __expf(x.z - mx); p.w = __expf(x.w - mx);

    float sm = p.x + p.y + p.z + p.w;
    sm = warp_sum(sm);
    if (lane == 0) red[warp] = sm;
    __syncthreads();
    if (tid < 32) {
        float t = red[tid];
        t = warp_sum(t);
        if (tid == 0) red[0] = t;
    }
    __syncthreads();
    float denom = red[0];
    __syncthreads();

    float4 m = m4p[tid];
    float4 a0;
    float inv = 1.f / denom;
    a0.x = p.x * inv * m.x; a0.y = p.y * inv * m.y;
    a0.z = p.z * inv * m.z; a0.w = p.w * inv * m.w;

    float s2 = a0.x + a0.y + a0.z + a0.w;
    s2 = warp_sum(s2);
    if (lane == 0) red[warp] = s2;
    __syncthreads();
    if (tid < 32) {
        float t = red[tid];
        t = warp_sum(t);
        if (tid == 0) red[0] = t;
    }
    __syncthreads();
    float inv2 = 1.f / (red[0] + 1e-20f);

    float4 a;
    a.x = a0.x * inv2; a.y = a0.y * inv2; a.z = a0.z * inv2; a.w = a0.w * inv2;
    attn1[tid] = a;
    attn2[tid] = a;

    out[b * HH + tid] = 0.f;
}

// ---------------------------------------------------------------------------
// K4: c_t[b][h] += sum_{s in chunk} attn[b,s] * eo[b,s,h]
// Static grid (R9 best); eo streamed with ld.global.cs.
// ---------------------------------------------------------------------------
#define K4_CHUNK 64
__global__ void __launch_bounds__(128) k_context(const float* __restrict__ eo,
                                                 float* __restrict__ out) {
    int b  = blockIdx.y;
    int s0 = blockIdx.x * K4_CHUNK;
    int t  = blockIdx.z * 128 + threadIdx.x;
    const float* attn = out + BB * HH + b * SS;
    const float4* eob = reinterpret_cast<const float4*>(eo + ((size_t)b * SS) * HH);

    float4 acc = make_float4(0.f, 0.f, 0.f, 0.f);
#pragma unroll 4
    for (int i = 0; i < K4_CHUNK; i++) {
        int s = s0 + i;
        float a  = __ldg(attn + s);
        float4 e = ldcs4(eob + (size_t)s * (HH / 4) + t);
        acc.x += a * e.x; acc.y += a * e.y;
        acc.z += a * e.z; acc.w += a * e.w;
    }
    float* ct = out + b * HH + t * 4;
    atomicAdd(ct + 0, acc.x);
    atomicAdd(ct + 1, acc.y);
    atomicAdd(ct + 2, acc.z);
    atomicAdd(ct + 3, acc.w);
}

// ---------------------------------------------------------------------------
extern "C" void kernel_launch(void* const* d_in, const int* in_sizes, int n_in,
                              void* d_out, int out_size) {
    const float* s_t_hat = (const float*)d_in[0];
    const float* enc_out = (const float*)d_in[1];
    const float* enc_fea = (const float*)d_in[2];
    const float* mask    = (const float*)d_in[3];
    const float* cov     = (const float*)d_in[4];
    const float* W_dec   = (const float*)d_in[5];
    const float* b_dec   = (const float*)d_in[6];
    const float* W_c     = (const float*)d_in[7];
    const float* v       = (const float*)d_in[8];
    float* out = (float*)d_out;

    float* scores = out + BB * HH + 2 * BB * SS;

    k_decproj<<<dim3(128, 4), 256>>>(s_t_hat, W_dec, b_dec, scores);
    k_scores<<<dim3(SS / SC_CHUNK, BB, 2), 128>>>(enc_fea, cov, W_c, v, scores);
    k_softmax<<<BB, 1024>>>(mask, out);
    k_context<<<dim3(SS / K4_CHUNK, BB, 2), 128>>>(enc_out, out);
}